// round 2
// baseline (speedup 1.0000x reference)
#include <cuda_runtime.h>

#define NN 50000
#define D  128
#define DO 64

// Scratch (device globals; no allocation allowed)
__device__ float g_agg [NN * D];   // layer-1 neighbor sum (128)
__device__ float g_cnt [NN];       // in-degree
__device__ float g_hl  [NN * DO];  // h @ W2_l   (to be scattered, 64-dim)
__device__ float g_base[NN * DO];  // h @ W2_r + b2 (row-local part of layer 2)
__device__ float g_agg2[NN * DO];  // layer-2 neighbor sum (64)
__device__ int   g_idx64;          // 1 if edge_index stored as int64, 0 if int32

// ---------------------------------------------------------------------------
// Detect edge_index dtype. Reads only within the first 2E*4 bytes (safe for
// both int32 and int64 storage). If int64: odd int32 words are high words = 0
// (indices < 50000). If int32: odd words are uniform in [0,50000) -> nonzero
// with probability 1 - (1/50000)^512.
// ---------------------------------------------------------------------------
__global__ void detect_kernel(const int* __restrict__ ei, int E) {
    int n = E < 512 ? E : 512;
    int hi_nonzero = 0;
    for (int i = 0; i < n; i++)
        if (ei[2 * i + 1] != 0) hi_nonzero = 1;
    g_idx64 = hi_nonzero ? 0 : 1;
}

__device__ __forceinline__ int load_idx(const void* ei, long long pos) {
    if (g_idx64) return (int)((const long long*)ei)[pos];
    return ((const int*)ei)[pos];
}

// ---------------------------------------------------------------------------
// Scatter 1: for each edge (src,dst): g_agg[dst] += x[src]; g_cnt[dst] += 1
// one warp per edge; lane handles 4 floats (float4 coalesced gather)
// ---------------------------------------------------------------------------
__global__ void scatter1_kernel(const float* __restrict__ x,
                                const void* __restrict__ ei, int E) {
    long long t = (long long)blockIdx.x * blockDim.x + threadIdx.x;
    int e = (int)(t >> 5);
    if (e >= E) return;
    int lane = (int)(t & 31);
    int src = load_idx(ei, e);
    int dst = load_idx(ei, (long long)E + e);
    float4 v = *(const float4*)(x + (size_t)src * D + lane * 4);
    float* p = g_agg + (size_t)dst * D + lane * 4;
    atomicAdd(p + 0, v.x);
    atomicAdd(p + 1, v.y);
    atomicAdd(p + 2, v.z);
    atomicAdd(p + 3, v.w);
    if (lane == 0) atomicAdd(g_cnt + dst, 1.0f);
}

// ---------------------------------------------------------------------------
// Scatter 2: for each edge: g_agg2[dst] += g_hl[src]   (64 floats)
// 16 threads per edge, float4 each
// ---------------------------------------------------------------------------
__global__ void scatter2_kernel(const void* __restrict__ ei, int E) {
    long long t = (long long)blockIdx.x * blockDim.x + threadIdx.x;
    int e = (int)(t >> 4);
    if (e >= E) return;
    int lane = (int)(t & 15);
    int src = load_idx(ei, e);
    int dst = load_idx(ei, (long long)E + e);
    float4 v = *(const float4*)(g_hl + (size_t)src * DO + lane * 4);
    float* p = g_agg2 + (size_t)dst * DO + lane * 4;
    atomicAdd(p + 0, v.x);
    atomicAdd(p + 1, v.y);
    atomicAdd(p + 2, v.z);
    atomicAdd(p + 3, v.w);
}

// ---------------------------------------------------------------------------
// Fused layer kernel (persistent, 148 blocks x 256 threads = 8 warps):
//   smem: W1_l (64KB) + W1_r (64KB) + W2_l (32KB) + W2_r (32KB) + row bufs
//   per warp per row:
//     h    = relu( (agg/max(cnt,1)) @ W1_l + b1 + x @ W1_r )   [128]
//     hl   = h @ W2_l                                          [64]  -> g_hl
//     base = h @ W2_r + b2                                     [64]  -> g_base
// ---------------------------------------------------------------------------
#define L1_SMEM_FLOATS (16384 + 16384 + 8192 + 8192 + 8 * 384)
#define L1_SMEM_BYTES  (L1_SMEM_FLOATS * 4)

__global__ void layer1_kernel(const float* __restrict__ x,
                              const float* __restrict__ W1l,
                              const float* __restrict__ b1,
                              const float* __restrict__ W1r,
                              const float* __restrict__ W2l,
                              const float* __restrict__ b2,
                              const float* __restrict__ W2r) {
    extern __shared__ float sm[];
    float* sW1l = sm;
    float* sW1r = sm + 16384;
    float* sW2l = sm + 32768;
    float* sW2r = sm + 40960;
    float* sRow = sm + 49152;  // 8 warps * 384 floats (a | x | h)

    const int tid = threadIdx.x;
    for (int i = tid; i < 16384; i += 256) { sW1l[i] = W1l[i]; sW1r[i] = W1r[i]; }
    for (int i = tid; i < 8192;  i += 256) { sW2l[i] = W2l[i]; sW2r[i] = W2r[i]; }
    __syncthreads();

    const int warp = tid >> 5;
    const int lane = tid & 31;
    float* sA = sRow + warp * 384;
    float* sX = sA + 128;
    float* sH = sA + 256;

    for (int base = blockIdx.x * 8; base < NN; base += gridDim.x * 8) {
        int row = base + warp;
        if (row < NN) {
            float inv = 1.0f / fmaxf(g_cnt[row], 1.0f);
            float4 av = *(const float4*)(g_agg + (size_t)row * D + lane * 4);
            float4 xv = *(const float4*)(x + (size_t)row * D + lane * 4);
            ((float4*)sA)[lane] = make_float4(av.x * inv, av.y * inv, av.z * inv, av.w * inv);
            ((float4*)sX)[lane] = xv;
            __syncwarp();

            // stage 1: this lane computes output columns 4*lane .. 4*lane+3
            float4 bl = *(const float4*)(b1 + lane * 4);
            float4 accL = make_float4(0.f, 0.f, 0.f, 0.f);
            float4 accR = make_float4(0.f, 0.f, 0.f, 0.f);
#pragma unroll 4
            for (int k = 0; k < 128; k++) {
                float a  = sA[k];
                float xk = sX[k];
                float4 wl = ((const float4*)(sW1l + k * 128))[lane];
                float4 wr = ((const float4*)(sW1r + k * 128))[lane];
                accL.x += a * wl.x;  accR.x += xk * wr.x;
                accL.y += a * wl.y;  accR.y += xk * wr.y;
                accL.z += a * wl.z;  accR.z += xk * wr.z;
                accL.w += a * wl.w;  accR.w += xk * wr.w;
            }
            float4 h4;
            h4.x = fmaxf(accL.x + accR.x + bl.x, 0.f);
            h4.y = fmaxf(accL.y + accR.y + bl.y, 0.f);
            h4.z = fmaxf(accL.z + accR.z + bl.z, 0.f);
            h4.w = fmaxf(accL.w + accR.w + bl.w, 0.f);
            ((float4*)sH)[lane] = h4;
            __syncwarp();

            // stage 2: lane computes cols 2*lane,2*lane+1 of hl and base
            float2 b2v = *(const float2*)(b2 + lane * 2);
            float2 aL = make_float2(0.f, 0.f);
            float2 aR = make_float2(b2v.x, b2v.y);
#pragma unroll 4
            for (int k = 0; k < 128; k++) {
                float h = sH[k];
                float2 wl = ((const float2*)(sW2l + k * 64))[lane];
                float2 wr = ((const float2*)(sW2r + k * 64))[lane];
                aL.x += h * wl.x;  aL.y += h * wl.y;
                aR.x += h * wr.x;  aR.y += h * wr.y;
            }
            *(float2*)(g_hl   + (size_t)row * DO + lane * 2) = aL;
            *(float2*)(g_base + (size_t)row * DO + lane * 2) = aR;
            __syncwarp();
        }
    }
}

// ---------------------------------------------------------------------------
// Final: out = g_agg2 / max(cnt,1) + g_base
// ---------------------------------------------------------------------------
__global__ void finish_kernel(float* __restrict__ out) {
    int i = blockIdx.x * blockDim.x + threadIdx.x;
    if (i >= NN * DO) return;
    int row = i >> 6;
    float inv = 1.0f / fmaxf(g_cnt[row], 1.0f);
    out[i] = g_agg2[i] * inv + g_base[i];
}

extern "C" void kernel_launch(void* const* d_in, const int* in_sizes, int n_in,
                              void* d_out, int out_size) {
    const float* x   = (const float*)d_in[0];
    const void*  ei  = d_in[1];
    const float* W1l = (const float*)d_in[2];
    const float* b1  = (const float*)d_in[3];
    const float* W1r = (const float*)d_in[4];
    const float* W2l = (const float*)d_in[5];
    const float* b2  = (const float*)d_in[6];
    const float* W2r = (const float*)d_in[7];
    float* out = (float*)d_out;

    int E = in_sizes[1] / 2;

    void *p_agg, *p_cnt, *p_agg2;
    cudaGetSymbolAddress(&p_agg,  g_agg);
    cudaGetSymbolAddress(&p_cnt,  g_cnt);
    cudaGetSymbolAddress(&p_agg2, g_agg2);

    cudaFuncSetAttribute(layer1_kernel,
                         cudaFuncAttributeMaxDynamicSharedMemorySize, L1_SMEM_BYTES);

    cudaMemsetAsync(p_agg,  0, (size_t)NN * D  * sizeof(float));
    cudaMemsetAsync(p_cnt,  0, (size_t)NN      * sizeof(float));
    cudaMemsetAsync(p_agg2, 0, (size_t)NN * DO * sizeof(float));

    detect_kernel<<<1, 1>>>((const int*)ei, E);

    // layer 1 aggregation
    {
        long long threads = (long long)E * 32;
        int blocks = (int)((threads + 255) / 256);
        scatter1_kernel<<<blocks, 256>>>(x, ei, E);
    }

    // fused: layer-1 update + relu + layer-2 row-local GEMMs
    layer1_kernel<<<148, 256, L1_SMEM_BYTES>>>(x, W1l, b1, W1r, W2l, b2, W2r);

    // layer 2 aggregation (64-dim, on hl = h @ W2_l)
    {
        long long threads = (long long)E * 16;
        int blocks = (int)((threads + 255) / 256);
        scatter2_kernel<<<blocks, 256>>>(ei, E);
    }

    // combine
    finish_kernel<<<(NN * DO + 255) / 256, 256>>>(out);
}

// round 3
// speedup vs baseline: 1.3498x; 1.3498x over previous
#include <cuda_runtime.h>

#define NN 50000
#define D  128
#define DO 64
#define EMAX 1048576

// Scratch (device globals; no allocation allowed)
__device__ float g_agg [NN * D];   // normalized layer-1 neighbor mean (128)
__device__ float g_hl  [NN * DO];  // h @ W2_l   (to be gathered, 64-dim)
__device__ float g_base[NN * DO];  // h @ W2_r + b2 (row-local part of layer 2)
__device__ int   g_cnt [NN];       // in-degree
__device__ int   g_off [NN];       // CSR row offsets (by dst)
__device__ int   g_cur [NN];       // fill cursors
__device__ int   g_csr [EMAX];     // src node per edge, grouped by dst
__device__ int   g_idx64;          // 1 if edge_index stored as int64, 0 if int32

// ---------------------------------------------------------------------------
// Detect edge_index dtype. Reads only within the first 2E*4 bytes (safe under
// both interpretations). int64 storage -> odd words are high words == 0.
// ---------------------------------------------------------------------------
__global__ void detect_kernel(const int* __restrict__ ei, int E) {
    int n = E < 512 ? E : 512;
    int i = threadIdx.x;
    int nz = (i < n && ei[2 * i + 1] != 0) ? 1 : 0;
    int any = __syncthreads_or(nz);
    if (i == 0) g_idx64 = any ? 0 : 1;
}

__device__ __forceinline__ int load_idx(const void* ei, long long pos) {
    if (g_idx64) return (int)((const long long*)ei)[pos];
    return ((const int*)ei)[pos];
}

// ---------------------------------------------------------------------------
// CSR build: histogram of dst
// ---------------------------------------------------------------------------
__global__ void hist_kernel(const void* __restrict__ ei, int E) {
    int e = blockIdx.x * blockDim.x + threadIdx.x;
    if (e >= E) return;
    int dst = load_idx(ei, (long long)E + e);
    atomicAdd(&g_cnt[dst], 1);
}

// Single-block exclusive scan over g_cnt -> g_off (also copies to g_cur)
__global__ void scan_kernel() {
    __shared__ int ssum[1024];
    const int T = 1024;
    const int CH = (NN + T - 1) / T;   // 49
    int t = threadIdx.x;
    int beg = t * CH;
    int end = beg + CH < NN ? beg + CH : NN;
    int s = 0;
    for (int i = beg; i < end; i++) s += g_cnt[i];
    ssum[t] = s;
    __syncthreads();
    // Hillis-Steele inclusive scan over 1024 partials
    for (int d = 1; d < T; d <<= 1) {
        int v = (t >= d) ? ssum[t - d] : 0;
        __syncthreads();
        ssum[t] += v;
        __syncthreads();
    }
    int run = ssum[t] - s;  // exclusive prefix for this chunk
    for (int i = beg; i < end; i++) {
        g_off[i] = run;
        g_cur[i] = run;
        run += g_cnt[i];
    }
}

__global__ void fill_kernel(const void* __restrict__ ei, int E) {
    int e = blockIdx.x * blockDim.x + threadIdx.x;
    if (e >= E) return;
    int src = load_idx(ei, e);
    int dst = load_idx(ei, (long long)E + e);
    int pos = atomicAdd(&g_cur[dst], 1);
    g_csr[pos] = src;
}

// ---------------------------------------------------------------------------
// Aggregation 1 (gather): warp per dst node; mean of x rows -> g_agg
// ---------------------------------------------------------------------------
__global__ void agg1_kernel(const float* __restrict__ x) {
    int t = blockIdx.x * blockDim.x + threadIdx.x;
    int node = t >> 5;
    if (node >= NN) return;
    int lane = t & 31;
    int beg = g_off[node];
    int deg = g_cnt[node];
    float4 acc = make_float4(0.f, 0.f, 0.f, 0.f);
    for (int i = 0; i < deg; i++) {
        int src = g_csr[beg + i];
        float4 v = *(const float4*)(x + (size_t)src * D + lane * 4);
        acc.x += v.x; acc.y += v.y; acc.z += v.z; acc.w += v.w;
    }
    float inv = 1.0f / (float)(deg > 0 ? deg : 1);
    *(float4*)(g_agg + (size_t)node * D + lane * 4) =
        make_float4(acc.x * inv, acc.y * inv, acc.z * inv, acc.w * inv);
}

// ---------------------------------------------------------------------------
// Fused layer kernel (persistent, 148 blocks x 256 threads = 8 warps):
//   smem: W1_l (64KB) + W1_r (64KB) + W2_l (32KB) + W2_r (32KB) + row bufs
//   per warp per row:
//     h    = relu( g_agg @ W1_l + b1 + x @ W1_r )   [128]
//     hl   = h @ W2_l                               [64]  -> g_hl
//     base = h @ W2_r + b2                          [64]  -> g_base
// ---------------------------------------------------------------------------
#define L1_SMEM_FLOATS (16384 + 16384 + 8192 + 8192 + 8 * 384)
#define L1_SMEM_BYTES  (L1_SMEM_FLOATS * 4)

__global__ void layer1_kernel(const float* __restrict__ x,
                              const float* __restrict__ W1l,
                              const float* __restrict__ b1,
                              const float* __restrict__ W1r,
                              const float* __restrict__ W2l,
                              const float* __restrict__ b2,
                              const float* __restrict__ W2r) {
    extern __shared__ float sm[];
    float* sW1l = sm;
    float* sW1r = sm + 16384;
    float* sW2l = sm + 32768;
    float* sW2r = sm + 40960;
    float* sRow = sm + 49152;  // 8 warps * 384 floats (a | x | h)

    const int tid = threadIdx.x;
    for (int i = tid; i < 16384; i += 256) { sW1l[i] = W1l[i]; sW1r[i] = W1r[i]; }
    for (int i = tid; i < 8192;  i += 256) { sW2l[i] = W2l[i]; sW2r[i] = W2r[i]; }
    __syncthreads();

    const int warp = tid >> 5;
    const int lane = tid & 31;
    float* sA = sRow + warp * 384;
    float* sX = sA + 128;
    float* sH = sA + 256;

    for (int base = blockIdx.x * 8; base < NN; base += gridDim.x * 8) {
        int row = base + warp;
        if (row < NN) {
            ((float4*)sA)[lane] = *(const float4*)(g_agg + (size_t)row * D + lane * 4);
            ((float4*)sX)[lane] = *(const float4*)(x + (size_t)row * D + lane * 4);
            __syncwarp();

            // stage 1: this lane computes output columns 4*lane .. 4*lane+3
            float4 bl = *(const float4*)(b1 + lane * 4);
            float4 accL = make_float4(0.f, 0.f, 0.f, 0.f);
            float4 accR = make_float4(0.f, 0.f, 0.f, 0.f);
#pragma unroll 4
            for (int k = 0; k < 128; k++) {
                float a  = sA[k];
                float xk = sX[k];
                float4 wl = ((const float4*)(sW1l + k * 128))[lane];
                float4 wr = ((const float4*)(sW1r + k * 128))[lane];
                accL.x += a * wl.x;  accR.x += xk * wr.x;
                accL.y += a * wl.y;  accR.y += xk * wr.y;
                accL.z += a * wl.z;  accR.z += xk * wr.z;
                accL.w += a * wl.w;  accR.w += xk * wr.w;
            }
            float4 h4;
            h4.x = fmaxf(accL.x + accR.x + bl.x, 0.f);
            h4.y = fmaxf(accL.y + accR.y + bl.y, 0.f);
            h4.z = fmaxf(accL.z + accR.z + bl.z, 0.f);
            h4.w = fmaxf(accL.w + accR.w + bl.w, 0.f);
            ((float4*)sH)[lane] = h4;
            __syncwarp();

            // stage 2: lane computes cols 2*lane,2*lane+1 of hl and base
            float2 b2v = *(const float2*)(b2 + lane * 2);
            float2 aL = make_float2(0.f, 0.f);
            float2 aR = make_float2(b2v.x, b2v.y);
#pragma unroll 4
            for (int k = 0; k < 128; k++) {
                float h = sH[k];
                float2 wl = ((const float2*)(sW2l + k * 64))[lane];
                float2 wr = ((const float2*)(sW2r + k * 64))[lane];
                aL.x += h * wl.x;  aL.y += h * wl.y;
                aR.x += h * wr.x;  aR.y += h * wr.y;
            }
            *(float2*)(g_hl   + (size_t)row * DO + lane * 2) = aL;
            *(float2*)(g_base + (size_t)row * DO + lane * 2) = aR;
            __syncwarp();
        }
    }
}

// ---------------------------------------------------------------------------
// Aggregation 2 + finish (gather): warp per dst node
//   out = mean_j(g_hl[src_j]) + g_base
// ---------------------------------------------------------------------------
__global__ void agg2_kernel(float* __restrict__ out) {
    int t = blockIdx.x * blockDim.x + threadIdx.x;
    int node = t >> 5;
    if (node >= NN) return;
    int lane = t & 31;
    int beg = g_off[node];
    int deg = g_cnt[node];
    float2 acc = make_float2(0.f, 0.f);
    for (int i = 0; i < deg; i++) {
        int src = g_csr[beg + i];
        float2 v = *(const float2*)(g_hl + (size_t)src * DO + lane * 2);
        acc.x += v.x; acc.y += v.y;
    }
    float inv = 1.0f / (float)(deg > 0 ? deg : 1);
    float2 b = *(const float2*)(g_base + (size_t)node * DO + lane * 2);
    *(float2*)(out + (size_t)node * DO + lane * 2) =
        make_float2(acc.x * inv + b.x, acc.y * inv + b.y);
}

extern "C" void kernel_launch(void* const* d_in, const int* in_sizes, int n_in,
                              void* d_out, int out_size) {
    const float* x   = (const float*)d_in[0];
    const void*  ei  = d_in[1];
    const float* W1l = (const float*)d_in[2];
    const float* b1  = (const float*)d_in[3];
    const float* W1r = (const float*)d_in[4];
    const float* W2l = (const float*)d_in[5];
    const float* b2  = (const float*)d_in[6];
    const float* W2r = (const float*)d_in[7];
    float* out = (float*)d_out;

    int E = in_sizes[1] / 2;
    if (E > EMAX) E = EMAX;

    void* p_cnt;
    cudaGetSymbolAddress(&p_cnt, g_cnt);

    cudaFuncSetAttribute(layer1_kernel,
                         cudaFuncAttributeMaxDynamicSharedMemorySize, L1_SMEM_BYTES);

    cudaMemsetAsync(p_cnt, 0, (size_t)NN * sizeof(int));

    detect_kernel<<<1, 512>>>((const int*)ei, E);

    // CSR build (by dst), reused by both layers
    hist_kernel<<<(E + 255) / 256, 256>>>(ei, E);
    scan_kernel<<<1, 1024>>>();
    fill_kernel<<<(E + 255) / 256, 256>>>(ei, E);

    // layer 1 aggregation (gather, no atomics)
    agg1_kernel<<<(NN * 32 + 255) / 256, 256>>>(x);

    // fused: layer-1 update + relu + layer-2 row-local GEMMs
    layer1_kernel<<<148, 256, L1_SMEM_BYTES>>>(x, W1l, b1, W1r, W2l, b2, W2r);

    // layer 2 aggregation + combine (gather, no atomics)
    agg2_kernel<<<(NN * 32 + 255) / 256, 256>>>(out);
}

// round 5
// speedup vs baseline: 2.7633x; 2.0471x over previous
#include <cuda_runtime.h>
#include <cstdint>

#define NN 50000
#define D  128
#define DO 64
#define EMAX 1048576

// Scratch (device globals; no allocation allowed)
__device__ float g_agg [NN * D];   // normalized layer-1 neighbor mean (128)
__device__ float g_h   [NN * D];   // relu(layer-1 output) (128)
__device__ float g_hl  [NN * DO];  // h @ W2_l (gathered by layer 2)
__device__ float g_base[NN * DO];  // h @ W2_r + b2
__device__ int   g_cnt [NN];
__device__ int   g_off [NN];
__device__ int   g_cur [NN];
__device__ int   g_csr [EMAX];
__device__ int   g_idx64;

// ---------------------------------------------------------------------------
__global__ void detect_kernel(const int* __restrict__ ei, int E) {
    int n = E < 512 ? E : 512;
    int i = threadIdx.x;
    int nz = (i < n && ei[2 * i + 1] != 0) ? 1 : 0;
    int any = __syncthreads_or(nz);
    if (i == 0) g_idx64 = any ? 0 : 1;
}

__device__ __forceinline__ int load_idx(const void* ei, long long pos) {
    if (g_idx64) return (int)((const long long*)ei)[pos];
    return ((const int*)ei)[pos];
}

__global__ void hist_kernel(const void* __restrict__ ei, int E) {
    int e = blockIdx.x * blockDim.x + threadIdx.x;
    if (e >= E) return;
    atomicAdd(&g_cnt[load_idx(ei, (long long)E + e)], 1);
}

__global__ void scan_kernel() {
    __shared__ int ssum[1024];
    const int T = 1024;
    const int CH = (NN + T - 1) / T;
    int t = threadIdx.x;
    int beg = t * CH;
    int end = beg + CH < NN ? beg + CH : NN;
    int s = 0;
    for (int i = beg; i < end; i++) s += g_cnt[i];
    ssum[t] = s;
    __syncthreads();
    for (int d = 1; d < T; d <<= 1) {
        int v = (t >= d) ? ssum[t - d] : 0;
        __syncthreads();
        ssum[t] += v;
        __syncthreads();
    }
    int run = ssum[t] - s;
    for (int i = beg; i < end; i++) {
        g_off[i] = run; g_cur[i] = run;
        run += g_cnt[i];
    }
}

__global__ void fill_kernel(const void* __restrict__ ei, int E) {
    int e = blockIdx.x * blockDim.x + threadIdx.x;
    if (e >= E) return;
    int src = load_idx(ei, e);
    int dst = load_idx(ei, (long long)E + e);
    g_csr[atomicAdd(&g_cur[dst], 1)] = src;
}

// ---------------------------------------------------------------------------
// Aggregation 1 (gather): warp per dst node; mean of x rows -> g_agg
// ---------------------------------------------------------------------------
__global__ void agg1_kernel(const float* __restrict__ x) {
    int t = blockIdx.x * blockDim.x + threadIdx.x;
    int node = t >> 5;
    if (node >= NN) return;
    int lane = t & 31;
    int beg = g_off[node];
    int deg = g_cnt[node];
    float4 acc = make_float4(0.f, 0.f, 0.f, 0.f);
    for (int i = 0; i < deg; i++) {
        int src = g_csr[beg + i];
        float4 v = *(const float4*)(x + (size_t)src * D + lane * 4);
        acc.x += v.x; acc.y += v.y; acc.z += v.z; acc.w += v.w;
    }
    float inv = 1.0f / (float)(deg > 0 ? deg : 1);
    *(float4*)(g_agg + (size_t)node * D + lane * 4) =
        make_float4(acc.x * inv, acc.y * inv, acc.z * inv, acc.w * inv);
}

// ---------------------------------------------------------------------------
// tf32 helpers
// ---------------------------------------------------------------------------
__device__ __forceinline__ uint32_t f2tf32(float f) {
    uint32_t r;
    asm("cvt.rna.tf32.f32 %0, %1;" : "=r"(r) : "f"(f));
    return r;
}

__device__ __forceinline__ void mma_tf32(float& d0, float& d1, float& d2, float& d3,
                                         uint32_t a0, uint32_t a1, uint32_t a2, uint32_t a3,
                                         uint32_t b0, uint32_t b1) {
    asm volatile(
        "mma.sync.aligned.m16n8k8.row.col.f32.tf32.tf32.f32 "
        "{%0,%1,%2,%3}, {%4,%5,%6,%7}, {%8,%9}, {%0,%1,%2,%3};"
        : "+f"(d0), "+f"(d1), "+f"(d2), "+f"(d3)
        : "r"(a0), "r"(a1), "r"(a2), "r"(a3), "r"(b0), "r"(b1));
}

// ---------------------------------------------------------------------------
// GEMM1: h = relu([agg | x] @ [W1l ; W1r] + b1)   (M=NN, K=256, N=128)
// Persistent 148 CTAs, tile 128x128, 8 warps (2x4), warp tile 64x32.
// smem: sW 256x132 tf32 (132KB) + sA 128x36 tf32 (18KB)
// ---------------------------------------------------------------------------
#define SW1_STR 132
#define SA_STR  36
#define G1_SMEM ((256 * SW1_STR + 128 * SA_STR) * 4)
#define NTILES  ((NN + 127) / 128)

__global__ void __launch_bounds__(256, 1)
gemm1_kernel(const float* __restrict__ x,
             const float* __restrict__ W1l,
             const float* __restrict__ b1,
             const float* __restrict__ W1r) {
    extern __shared__ uint32_t smu[];
    uint32_t* sW = smu;
    uint32_t* sA = smu + 256 * SW1_STR;

    const int tid  = threadIdx.x;
    const int wid  = tid >> 5;
    const int lane = tid & 31;
    const int gid  = lane >> 2;   // group id (row within fragment)
    const int tig  = lane & 3;    // thread in group
    const int wm   = wid & 1;     // 2 warp-rows  (64 rows each)
    const int wn   = wid >> 1;    // 4 warp-cols  (32 cols each)

    // Load + convert weights once: k<128 -> W1l, k>=128 -> W1r
    for (int i = tid; i < 256 * 128; i += 256) {
        int k = i >> 7, n = i & 127;
        float w = (k < 128) ? W1l[k * 128 + n] : W1r[(k - 128) * 128 + n];
        sW[k * SW1_STR + n] = f2tf32(w);
    }
    __syncthreads();

    for (int t = blockIdx.x; t < NTILES; t += gridDim.x) {
        int tile_row = t * 128;
        float acc[4][4][4];
#pragma unroll
        for (int mt = 0; mt < 4; mt++)
#pragma unroll
            for (int nt = 0; nt < 4; nt++)
#pragma unroll
                for (int q = 0; q < 4; q++) acc[mt][nt][q] = 0.f;

        for (int c = 0; c < 8; c++) {  // k-chunks of 32 (0-3: agg, 4-7: x)
            // load A chunk: 128 rows x 32 k
#pragma unroll
            for (int i = tid; i < 1024; i += 256) {
                int r = i >> 3;
                int j = i & 7;
                int row = tile_row + r;
                float4 v = make_float4(0.f, 0.f, 0.f, 0.f);
                if (row < NN) {
                    int kg = c * 32 + j * 4;
                    const float* src = (c < 4)
                        ? (g_agg + (size_t)row * D + kg)
                        : (x + (size_t)row * D + (kg - 128));
                    v = *(const float4*)src;
                }
                uint4 u;
                u.x = f2tf32(v.x); u.y = f2tf32(v.y);
                u.z = f2tf32(v.z); u.w = f2tf32(v.w);
                *(uint4*)(sA + r * SA_STR + j * 4) = u;
            }
            __syncthreads();

#pragma unroll
            for (int ks = 0; ks < 4; ks++) {
                int kk = ks * 8;
                int kg = c * 32 + kk;
                uint32_t b[4][2];
#pragma unroll
                for (int nt = 0; nt < 4; nt++) {
                    int n0 = wn * 32 + nt * 8 + gid;
                    b[nt][0] = sW[(kg + tig) * SW1_STR + n0];
                    b[nt][1] = sW[(kg + tig + 4) * SW1_STR + n0];
                }
                uint32_t a[4][4];
#pragma unroll
                for (int mt = 0; mt < 4; mt++) {
                    int m0 = wm * 64 + mt * 16;
                    a[mt][0] = sA[(m0 + gid) * SA_STR + kk + tig];
                    a[mt][1] = sA[(m0 + gid + 8) * SA_STR + kk + tig];
                    a[mt][2] = sA[(m0 + gid) * SA_STR + kk + tig + 4];
                    a[mt][3] = sA[(m0 + gid + 8) * SA_STR + kk + tig + 4];
                }
#pragma unroll
                for (int mt = 0; mt < 4; mt++)
#pragma unroll
                    for (int nt = 0; nt < 4; nt++)
                        mma_tf32(acc[mt][nt][0], acc[mt][nt][1],
                                 acc[mt][nt][2], acc[mt][nt][3],
                                 a[mt][0], a[mt][1], a[mt][2], a[mt][3],
                                 b[nt][0], b[nt][1]);
            }
            __syncthreads();
        }

        // epilogue: + b1, relu, store h
#pragma unroll
        for (int mt = 0; mt < 4; mt++) {
#pragma unroll
            for (int nt = 0; nt < 4; nt++) {
                int n0 = wn * 32 + nt * 8 + 2 * tig;
                float bb0 = b1[n0], bb1 = b1[n0 + 1];
                int r0 = tile_row + wm * 64 + mt * 16 + gid;
                if (r0 < NN) {
                    float2 v = make_float2(fmaxf(acc[mt][nt][0] + bb0, 0.f),
                                           fmaxf(acc[mt][nt][1] + bb1, 0.f));
                    *(float2*)(g_h + (size_t)r0 * D + n0) = v;
                }
                if (r0 + 8 < NN) {
                    float2 v = make_float2(fmaxf(acc[mt][nt][2] + bb0, 0.f),
                                           fmaxf(acc[mt][nt][3] + bb1, 0.f));
                    *(float2*)(g_h + (size_t)(r0 + 8) * D + n0) = v;
                }
            }
        }
    }
}

// ---------------------------------------------------------------------------
// GEMM2: [hl | base] = h @ [W2l | W2r]  (+b2 on base half)  (M=NN, K=128, N=128)
// ---------------------------------------------------------------------------
#define SW2_STR 132
#define G2_SMEM ((128 * SW2_STR + 128 * SA_STR) * 4)

__global__ void __launch_bounds__(256, 1)
gemm2_kernel(const float* __restrict__ W2l,
             const float* __restrict__ b2,
             const float* __restrict__ W2r) {
    extern __shared__ uint32_t smu[];
    uint32_t* sW = smu;
    uint32_t* sA = smu + 128 * SW2_STR;

    const int tid  = threadIdx.x;
    const int wid  = tid >> 5;
    const int lane = tid & 31;
    const int gid  = lane >> 2;
    const int tig  = lane & 3;
    const int wm   = wid & 1;
    const int wn   = wid >> 1;

    for (int i = tid; i < 128 * 128; i += 256) {
        int k = i >> 7, n = i & 127;
        float w = (n < 64) ? W2l[k * 64 + n] : W2r[k * 64 + (n - 64)];
        sW[k * SW2_STR + n] = f2tf32(w);
    }
    __syncthreads();

    for (int t = blockIdx.x; t < NTILES; t += gridDim.x) {
        int tile_row = t * 128;
        float acc[4][4][4];
#pragma unroll
        for (int mt = 0; mt < 4; mt++)
#pragma unroll
            for (int nt = 0; nt < 4; nt++)
#pragma unroll
                for (int q = 0; q < 4; q++) acc[mt][nt][q] = 0.f;

        for (int c = 0; c < 4; c++) {
#pragma unroll
            for (int i = tid; i < 1024; i += 256) {
                int r = i >> 3;
                int j = i & 7;
                int row = tile_row + r;
                float4 v = make_float4(0.f, 0.f, 0.f, 0.f);
                if (row < NN)
                    v = *(const float4*)(g_h + (size_t)row * D + c * 32 + j * 4);
                uint4 u;
                u.x = f2tf32(v.x); u.y = f2tf32(v.y);
                u.z = f2tf32(v.z); u.w = f2tf32(v.w);
                *(uint4*)(sA + r * SA_STR + j * 4) = u;
            }
            __syncthreads();

#pragma unroll
            for (int ks = 0; ks < 4; ks++) {
                int kk = ks * 8;
                int kg = c * 32 + kk;
                uint32_t b[4][2];
#pragma unroll
                for (int nt = 0; nt < 4; nt++) {
                    int n0 = wn * 32 + nt * 8 + gid;
                    b[nt][0] = sW[(kg + tig) * SW2_STR + n0];
                    b[nt][1] = sW[(kg + tig + 4) * SW2_STR + n0];
                }
                uint32_t a[4][4];
#pragma unroll
                for (int mt = 0; mt < 4; mt++) {
                    int m0 = wm * 64 + mt * 16;
                    a[mt][0] = sA[(m0 + gid) * SA_STR + kk + tig];
                    a[mt][1] = sA[(m0 + gid + 8) * SA_STR + kk + tig];
                    a[mt][2] = sA[(m0 + gid) * SA_STR + kk + tig + 4];
                    a[mt][3] = sA[(m0 + gid + 8) * SA_STR + kk + tig + 4];
                }
#pragma unroll
                for (int mt = 0; mt < 4; mt++)
#pragma unroll
                    for (int nt = 0; nt < 4; nt++)
                        mma_tf32(acc[mt][nt][0], acc[mt][nt][1],
                                 acc[mt][nt][2], acc[mt][nt][3],
                                 a[mt][0], a[mt][1], a[mt][2], a[mt][3],
                                 b[nt][0], b[nt][1]);
            }
            __syncthreads();
        }

        // epilogue: cols<64 -> g_hl; cols>=64 -> g_base (+b2)
#pragma unroll
        for (int mt = 0; mt < 4; mt++) {
#pragma unroll
            for (int nt = 0; nt < 4; nt++) {
                int n0 = wn * 32 + nt * 8 + 2 * tig;
                int r0 = tile_row + wm * 64 + mt * 16 + gid;
                if (n0 < 64) {
                    if (r0 < NN)
                        *(float2*)(g_hl + (size_t)r0 * DO + n0) =
                            make_float2(acc[mt][nt][0], acc[mt][nt][1]);
                    if (r0 + 8 < NN)
                        *(float2*)(g_hl + (size_t)(r0 + 8) * DO + n0) =
                            make_float2(acc[mt][nt][2], acc[mt][nt][3]);
                } else {
                    int nb = n0 - 64;
                    float bb0 = b2[nb], bb1 = b2[nb + 1];
                    if (r0 < NN)
                        *(float2*)(g_base + (size_t)r0 * DO + nb) =
                            make_float2(acc[mt][nt][0] + bb0, acc[mt][nt][1] + bb1);
                    if (r0 + 8 < NN)
                        *(float2*)(g_base + (size_t)(r0 + 8) * DO + nb) =
                            make_float2(acc[mt][nt][2] + bb0, acc[mt][nt][3] + bb1);
                }
            }
        }
    }
}

// ---------------------------------------------------------------------------
// Aggregation 2 + finish: out = mean_j(g_hl[src_j]) + g_base
// ---------------------------------------------------------------------------
__global__ void agg2_kernel(float* __restrict__ out) {
    int t = blockIdx.x * blockDim.x + threadIdx.x;
    int node = t >> 5;
    if (node >= NN) return;
    int lane = t & 31;
    int beg = g_off[node];
    int deg = g_cnt[node];
    float2 acc = make_float2(0.f, 0.f);
    for (int i = 0; i < deg; i++) {
        int src = g_csr[beg + i];
        float2 v = *(const float2*)(g_hl + (size_t)src * DO + lane * 2);
        acc.x += v.x; acc.y += v.y;
    }
    float inv = 1.0f / (float)(deg > 0 ? deg : 1);
    float2 b = *(const float2*)(g_base + (size_t)node * DO + lane * 2);
    *(float2*)(out + (size_t)node * DO + lane * 2) =
        make_float2(acc.x * inv + b.x, acc.y * inv + b.y);
}

extern "C" void kernel_launch(void* const* d_in, const int* in_sizes, int n_in,
                              void* d_out, int out_size) {
    const float* x   = (const float*)d_in[0];
    const void*  ei  = d_in[1];
    const float* W1l = (const float*)d_in[2];
    const float* b1  = (const float*)d_in[3];
    const float* W1r = (const float*)d_in[4];
    const float* W2l = (const float*)d_in[5];
    const float* b2  = (const float*)d_in[6];
    const float* W2r = (const float*)d_in[7];
    float* out = (float*)d_out;

    int E = in_sizes[1] / 2;
    if (E > EMAX) E = EMAX;

    void* p_cnt;
    cudaGetSymbolAddress(&p_cnt, g_cnt);

    cudaFuncSetAttribute(gemm1_kernel,
                         cudaFuncAttributeMaxDynamicSharedMemorySize, G1_SMEM);
    cudaFuncSetAttribute(gemm2_kernel,
                         cudaFuncAttributeMaxDynamicSharedMemorySize, G2_SMEM);

    cudaMemsetAsync(p_cnt, 0, (size_t)NN * sizeof(int));

    detect_kernel<<<1, 512>>>((const int*)ei, E);

    // CSR build (by dst), reused by both layers
    hist_kernel<<<(E + 255) / 256, 256>>>(ei, E);
    scan_kernel<<<1, 1024>>>();
    fill_kernel<<<(E + 255) / 256, 256>>>(ei, E);

    // layer 1 aggregation (gather, no atomics)
    agg1_kernel<<<(NN * 32 + 255) / 256, 256>>>(x);

    // tensor-core GEMMs
    gemm1_kernel<<<148, 256, G1_SMEM>>>(x, W1l, b1, W1r);
    gemm2_kernel<<<148, 256, G2_SMEM>>>(W2l, b2, W2r);

    // layer 2 aggregation + combine
    agg2_kernel<<<(NN * 32 + 255) / 256, 256>>>(out);
}